// round 13
// baseline (speedup 1.0000x reference)
#include <cuda_runtime.h>
#include <cstdint>

#define N_DIS 25000
#define N_MIR 25000
#define NN    50000
#define EE    600000
#define EMB   128
#define NB_SCAN 196   // ceil(50000/256)

#define BM 128
#define BN 128
#define BK 32
// smem tile sizes in 32-bit words
#define ATW 4096          // A tile: 128x32 permuted
#define BSTRIDE 264       // B tile row stride (16 rows of 2*128 + 8 pad)
#define BTW (16 * BSTRIDE)        // 4224
#define TILEW (ATW + BTW)         // 8320 words per buffer

// ---------------- scratch (static device globals: no allocs allowed) --------
__device__ float g_h   [(size_t)(NN + BM) * EMB];
__device__ float g_h1  [(size_t)(NN + BM) * EMB];
__device__ float g_agg [(size_t)(NN + BM) * EMB];
__device__ float g_inv [NN];
__device__ int   g_cnt [NN];
__device__ int   g_off [NN];
__device__ int   g_cur [NN];
__device__ int   g_esrc[EE];
__device__ int   g_bsum[NB_SCAN];

// ---------------- helpers ----------------------------------------------------
__device__ __forceinline__ uint32_t f2tf32(float x) {
    uint32_t r;
    asm("cvt.rna.tf32.f32 %0, %1;\n" : "=r"(r) : "f"(x));
    return r;
}
__device__ __forceinline__ void mma_tf32(float* d, const uint32_t* a,
                                         const uint32_t* b) {
    asm volatile(
        "mma.sync.aligned.m16n8k8.row.col.f32.tf32.tf32.f32 "
        "{%0,%1,%2,%3},{%4,%5,%6,%7},{%8,%9},{%0,%1,%2,%3};\n"
        : "+f"(d[0]), "+f"(d[1]), "+f"(d[2]), "+f"(d[3])
        : "r"(a[0]), "r"(a[1]), "r"(a[2]), "r"(a[3]), "r"(b[0]), "r"(b[1]));
}

// A permuted index: 16B slot per fragment quad.
// word(m,k) = ((m>>4)*8 + (m&7))*64
//           + (((k>>3)*16 + (k&3)*4 + ((m>>3)&1) + 2*((k>>2)&1)) ^ ((m&1)*16))
__device__ __forceinline__ int a_idx(int m, int k) {
    int base = ((((m >> 4) << 3) + (m & 7)) << 6);
    int off  = ((k >> 3) << 4) + ((k & 3) << 2) + ((m >> 3) & 1) +
               (((k >> 2) & 1) << 1);
    return base + (off ^ ((m & 1) << 4));
}

// ---------------- CSR build --------------------------------------------------
__global__ void zero_cnt_kernel() {
    int i = blockIdx.x * blockDim.x + threadIdx.x;
    if (i < NN) g_cnt[i] = 0;
}

__global__ void count_kernel(const int* __restrict__ dst) {
    int e = blockIdx.x * blockDim.x + threadIdx.x;
    if (e < EE) atomicAdd(&g_cnt[dst[e]], 1);
}

__global__ void scan1_kernel() {
    __shared__ int sh[256];
    int t = threadIdx.x;
    int i = blockIdx.x * 256 + t;
    int v = (i < NN) ? g_cnt[i] : 0;
    sh[t] = v;
    __syncthreads();
#pragma unroll
    for (int o = 1; o < 256; o <<= 1) {
        int x = (t >= o) ? sh[t - o] : 0;
        __syncthreads();
        sh[t] += x;
        __syncthreads();
    }
    if (i < NN) g_off[i] = sh[t] - v;
    if (t == 255) g_bsum[blockIdx.x] = sh[255];
}

__global__ void scan23_kernel() {
    __shared__ int ws[8];
    int t = threadIdx.x, b = blockIdx.x;
    int v = (t < b && t < NB_SCAN) ? g_bsum[t] : 0;
#pragma unroll
    for (int o = 16; o; o >>= 1) v += __shfl_down_sync(0xffffffffu, v, o);
    if ((t & 31) == 0) ws[t >> 5] = v;
    __syncthreads();
    if (t == 0) {
        int tot = 0;
#pragma unroll
        for (int j = 0; j < 8; ++j) tot += ws[j];
        ws[0] = tot;
    }
    __syncthreads();
    int base = ws[0];
    int i = b * 256 + t;
    if (i < NN) {
        int off = g_off[i] + base;
        g_off[i] = off;
        g_cur[i] = off;
        g_inv[i] = 1.0f / fmaxf((float)g_cnt[i], 1.0f);
    }
}

__global__ void fill_kernel(const int* __restrict__ src,
                            const int* __restrict__ dst) {
    int e = blockIdx.x * blockDim.x + threadIdx.x;
    if (e >= EE) return;
    int d = dst[e];
    int pos = atomicAdd(&g_cur[d], 1);
    g_esrc[pos] = src[e];
}

// ---------------- gather-mean ------------------------------------------------
__global__ void gather_kernel(const float* __restrict__ x) {
    int w    = (blockIdx.x * blockDim.x + threadIdx.x) >> 5;
    int lane = threadIdx.x & 31;
    if (w >= NN) return;
    int beg = g_off[w];
    int end = (w == NN - 1) ? EE : g_off[w + 1];

    float4 acc = make_float4(0.f, 0.f, 0.f, 0.f);
    int e = beg;
    for (; e + 1 < end; e += 2) {
        int s0 = g_esrc[e], s1 = g_esrc[e + 1];
        float4 v0 = reinterpret_cast<const float4*>(x + (size_t)s0 * EMB)[lane];
        float4 v1 = reinterpret_cast<const float4*>(x + (size_t)s1 * EMB)[lane];
        acc.x += v0.x + v1.x; acc.y += v0.y + v1.y;
        acc.z += v0.z + v1.z; acc.w += v0.w + v1.w;
    }
    if (e < end) {
        int s = g_esrc[e];
        float4 v = reinterpret_cast<const float4*>(x + (size_t)s * EMB)[lane];
        acc.x += v.x; acc.y += v.y; acc.z += v.z; acc.w += v.w;
    }
    float iv = g_inv[w];
    acc.x *= iv; acc.y *= iv; acc.z *= iv; acc.w *= iv;
    reinterpret_cast<float4*>(g_agg + (size_t)w * EMB)[lane] = acc;
}

// ---------------- unified TF32 GEMM ------------------------------------------
// C = A1@W1 (+ A2@W2) + bias, optional ReLU. N fixed = 128. Double-buffered
// smem with vectorized-fragment layouts: A frags load as LDS.128, B frag
// pairs as LDS.64 (bank-conflict-free both).

__device__ __forceinline__ void fetch_tile(const float* __restrict__ A,
                                           const float* __restrict__ W,
                                           int K, int k0, int row0, int M,
                                           int la_m, int lane, int q,
                                           float pa[16], float4 pb[4]) {
    int gk = k0 + lane;
    bool kok = gk < K;
#pragma unroll
    for (int i = 0; i < 16; ++i) {
        int gm = row0 + la_m + 8 * i;
        pa[i] = (kok && gm < M) ? A[(size_t)gm * K + gk] : 0.f;
    }
#pragma unroll
    for (int j = 0; j < 4; ++j) {
        int r = q + ((j & 1) << 2) + ((j >> 1) << 4);   // q, q+4, q+16, q+20
        int gkr = k0 + r;
        pb[j] = (gkr < K)
            ? *reinterpret_cast<const float4*>(W + (size_t)gkr * BN + 4 * lane)
            : make_float4(0.f, 0.f, 0.f, 0.f);
    }
}

__device__ __forceinline__ void sts_tile(uint32_t* __restrict__ Ab,
                                         uint32_t* __restrict__ Bb,
                                         const float pa[16], const float4 pb[4],
                                         int la_m, int lane, int q) {
#pragma unroll
    for (int i = 0; i < 16; ++i)
        Ab[a_idx(la_m + 8 * i, lane)] = f2tf32(pa[i]);
    int p = ((q >> 3) << 2) + (q & 3);
    uint4 v;
    v.x = f2tf32(pb[0].x); v.y = f2tf32(pb[1].x);
    v.z = f2tf32(pb[0].y); v.w = f2tf32(pb[1].y);
    *reinterpret_cast<uint4*>(Bb + p * BSTRIDE + 8 * lane) = v;
    v.x = f2tf32(pb[0].z); v.y = f2tf32(pb[1].z);
    v.z = f2tf32(pb[0].w); v.w = f2tf32(pb[1].w);
    *reinterpret_cast<uint4*>(Bb + p * BSTRIDE + 8 * lane + 4) = v;
    v.x = f2tf32(pb[2].x); v.y = f2tf32(pb[3].x);
    v.z = f2tf32(pb[2].y); v.w = f2tf32(pb[3].y);
    *reinterpret_cast<uint4*>(Bb + (p + 8) * BSTRIDE + 8 * lane) = v;
    v.x = f2tf32(pb[2].z); v.y = f2tf32(pb[3].z);
    v.z = f2tf32(pb[2].w); v.w = f2tf32(pb[3].w);
    *reinterpret_cast<uint4*>(Bb + (p + 8) * BSTRIDE + 8 * lane + 4) = v;
}

__device__ __forceinline__ void compute_tile(const uint32_t* __restrict__ As_,
                                             const uint32_t* __restrict__ Bs_,
                                             float acc[2][8][4],
                                             int wm, int wn, int g4, int tig) {
#pragma unroll
    for (int ks = 0; ks < 4; ++ks) {
        uint32_t af[2][4];
#pragma unroll
        for (int mt = 0; mt < 2; ++mt) {
            int t16 = wm * 2 + mt;
            int word = (((t16 << 3) + g4) << 6) +
                       (((ks << 4) + (tig << 2)) ^ ((g4 & 1) << 4));
            uint4 v = *reinterpret_cast<const uint4*>(As_ + word);
            af[mt][0] = v.x; af[mt][1] = v.y; af[mt][2] = v.z; af[mt][3] = v.w;
        }
#pragma unroll
        for (int nt = 0; nt < 8; ++nt) {
            int n = wn * 64 + nt * 8 + g4;
            uint2 bv = *reinterpret_cast<const uint2*>(
                Bs_ + ((ks << 2) + tig) * BSTRIDE + (n << 1));
            uint32_t bf[2] = {bv.x, bv.y};
            mma_tf32(acc[0][nt], af[0], bf);
            mma_tf32(acc[1][nt], af[1], bf);
        }
    }
}

__global__ __launch_bounds__(256, 2)
void gemm2(const float* __restrict__ A1, const float* __restrict__ W1,
           const float* __restrict__ A2, const float* __restrict__ W2,
           const float* __restrict__ bias, float* __restrict__ C,
           int M, int K1, int K2, int do_relu)
{
    extern __shared__ uint32_t smu[];

    const int t    = threadIdx.x;
    const int lane = t & 31;
    const int warp = t >> 5;
    const int wm   = warp & 3;
    const int wn   = warp >> 2;
    const int g4   = lane >> 2;
    const int tig  = lane & 3;
    const int row0 = blockIdx.x * BM;

    const int la_m = warp;                          // A loader: rows la_m + 8i
    const int q    = (warp & 3) + ((warp >> 2) << 3);  // B loader row base

    float acc[2][8][4];
#pragma unroll
    for (int mt = 0; mt < 2; ++mt)
#pragma unroll
        for (int nt = 0; nt < 8; ++nt)
#pragma unroll
            for (int j = 0; j < 4; ++j) acc[mt][nt][j] = 0.f;

    const int nk1 = (K1 + BK - 1) / BK;
    const int nk2 = (K2 + BK - 1) / BK;
    const int tot = nk1 + nk2;

    float  pa[16];
    float4 pb[4];

    fetch_tile(A1, W1, K1, 0, row0, M, la_m, lane, q, pa, pb);

#pragma unroll 1
    for (int tt = 0; tt < tot; ++tt) {
        uint32_t* Ab = smu + (tt & 1) * TILEW;
        uint32_t* Bb = Ab + ATW;
        sts_tile(Ab, Bb, pa, pb, la_m, lane, q);
        __syncthreads();                  // single barrier per tile

        if (tt + 1 < tot) {
            int ph = (tt + 1 >= nk1);
            int k0 = ((tt + 1) - (ph ? nk1 : 0)) * BK;
            fetch_tile(ph ? A2 : A1, ph ? W2 : W1, ph ? K2 : K1,
                       k0, row0, M, la_m, lane, q, pa, pb);
        }
        compute_tile(Ab, Bb, acc, wm, wn, g4, tig);
    }

    // epilogue
#pragma unroll
    for (int mt = 0; mt < 2; ++mt) {
        int r0 = row0 + wm * 32 + mt * 16 + g4;
#pragma unroll
        for (int nt = 0; nt < 8; ++nt) {
            int ccol = wn * 64 + nt * 8 + 2 * tig;
            float b0 = bias[ccol], b1 = bias[ccol + 1];
            float v0 = acc[mt][nt][0] + b0;
            float v1 = acc[mt][nt][1] + b1;
            float v2 = acc[mt][nt][2] + b0;
            float v3 = acc[mt][nt][3] + b1;
            if (do_relu) {
                v0 = fmaxf(v0, 0.f); v1 = fmaxf(v1, 0.f);
                v2 = fmaxf(v2, 0.f); v3 = fmaxf(v3, 0.f);
            }
            if (r0 < M)
                *reinterpret_cast<float2*>(C + (size_t)r0 * BN + ccol) =
                    make_float2(v0, v1);
            if (r0 + 8 < M)
                *reinterpret_cast<float2*>(C + (size_t)(r0 + 8) * BN + ccol) =
                    make_float2(v2, v3);
        }
    }
}

// ---------------- launch ----------------------------------------------------
extern "C" void kernel_launch(void* const* d_in, const int* in_sizes, int n_in,
                              void* d_out, int out_size) {
    const float* d_feat = (const float*)d_in[0];
    const float* m_feat = (const float*)d_in[1];
    const int*   src    = (const int*)  d_in[2];
    const int*   dst    = (const int*)  d_in[3];
    const float* W_d    = (const float*)d_in[4];
    const float* b_d    = (const float*)d_in[5];
    const float* W_m    = (const float*)d_in[6];
    const float* b_m    = (const float*)d_in[7];
    const float* W_s1   = (const float*)d_in[8];
    const float* W_n1   = (const float*)d_in[9];
    const float* b1     = (const float*)d_in[10];
    const float* W_s2   = (const float*)d_in[11];
    const float* W_n2   = (const float*)d_in[12];
    const float* b2     = (const float*)d_in[13];
    float* out = (float*)d_out;

    float *h, *h1, *agg;
    cudaGetSymbolAddress((void**)&h,   g_h);
    cudaGetSymbolAddress((void**)&h1,  g_h1);
    cudaGetSymbolAddress((void**)&agg, g_agg);

    const int GEMM_SMEM = 2 * TILEW * 4;     // 66560 B

    static cudaEvent_t ev_fork = nullptr, ev_join = nullptr;
    static int init_done = 0;
    if (!init_done) {
        cudaFuncSetAttribute(gemm2,
                             cudaFuncAttributeMaxDynamicSharedMemorySize,
                             GEMM_SMEM);
        cudaEventCreateWithFlags(&ev_fork, cudaEventDisableTiming);
        cudaEventCreateWithFlags(&ev_join, cudaEventDisableTiming);
        init_done = 1;
    }

    cudaStream_t main_s = 0;
    cudaStream_t aux_s  = cudaStreamPerThread;

    const int grid_embed  = (N_DIS + BM - 1) / BM;    // 196
    const int grid_layer  = (NN    + BM - 1) / BM;    // 391
    const int grid_edges  = (EE + 255) / 256;
    const int grid_nodes  = (NN + 255) / 256;
    const int grid_gather = (NN * 32 + 255) / 256;

    // ---- fork: embed1 on main; CSR chain + embed2 on aux
    cudaEventRecord(ev_fork, main_s);
    cudaStreamWaitEvent(aux_s, ev_fork, 0);

    gemm2<<<grid_embed, 256, GEMM_SMEM, main_s>>>(
        d_feat, W_d, d_feat, W_d, b_d, h, N_DIS, 383, 0, 0);

    zero_cnt_kernel<<<grid_nodes, 256, 0, aux_s>>>();
    count_kernel<<<grid_edges, 256, 0, aux_s>>>(dst);
    scan1_kernel<<<NB_SCAN, 256, 0, aux_s>>>();
    scan23_kernel<<<grid_nodes, 256, 0, aux_s>>>();
    fill_kernel<<<grid_edges, 256, 0, aux_s>>>(src, dst);
    gemm2<<<grid_embed, 256, GEMM_SMEM, aux_s>>>(
        m_feat, W_m, m_feat, W_m, b_m,
        h + (size_t)N_DIS * EMB, N_MIR, 495, 0, 0);

    cudaEventRecord(ev_join, aux_s);
    cudaStreamWaitEvent(main_s, ev_join, 0);

    // ---- layer 1: h1 = relu(h@Ws1 + agg@Wn1 + b1)
    gather_kernel<<<grid_gather, 256, 0, main_s>>>(h);
    gemm2<<<grid_layer, 256, GEMM_SMEM, main_s>>>(
        h, W_s1, agg, W_n1, b1, h1, NN, 128, 128, 1);

    // ---- layer 2: out = h1@Ws2 + agg2@Wn2 + b2
    gather_kernel<<<grid_gather, 256, 0, main_s>>>(h1);
    gemm2<<<grid_layer, 256, GEMM_SMEM, main_s>>>(
        h1, W_s2, agg, W_n2, b2, out, NN, 128, 128, 0);
}